// round 10
// baseline (speedup 1.0000x reference)
#include <cuda_runtime.h>
#include <math.h>

#define Dm   2048
#define Hh   16
#define KVh  8
#define HD   128
#define Ff   8192
#define Vv   32000
#define MAXP 4096
#define Bb   4
#define Ll   2
#define EPS  1e-6f
#define ATT_SCALE 0.08838834764831845f   // 1/sqrt(128)
#define NCHUNK 32
#define ROPE_C 0.21586735f                // ln(1e6)/64

// ---------------- scratch (allocation-free: __device__ globals) -------------
__device__ __align__(16) float g_x  [Dm*Bb];        // residual stream, [D][B]
__device__ __align__(16) float g_qkv[4096*Bb];      // q|k|v, [N][B]
__device__ __align__(16) float g_o  [Dm*Bb];        // attn out, [N][B]
__device__ __align__(16) float g_g  [Ff*Bb];        // mlp mid, [F][B]
__device__ __align__(16) float g_pacc[Bb*Hh*NCHUNK*HD];
__device__ float g_pm[Bb*Hh*NCHUNK];
__device__ float g_pl[Bb*Hh*NCHUNK];

__device__ __forceinline__ float sel4(float4 v, int b) {
    return (b == 0) ? v.x : (b == 1) ? v.y : (b == 2) ? v.z : v.w;
}

// ---------------- embed -----------------------------------------------------
__global__ void embed_k(const int* __restrict__ tok, const float* __restrict__ emb,
                        float* __restrict__ x) {
    cudaGridDependencySynchronize();
    int d = blockIdx.x * blockDim.x + threadIdx.x;
    int b = blockIdx.y;
    x[d*Bb + b] = emb[(size_t)tok[b]*Dm + d];
}

// =============================================================================
// batch-4 GEMV, 8 cols/block, compile-time D, flat 8-deep load batches.
// Optional fused rmsnorm: Sx2 accumulated in the SAME loop (x already loaded),
// xn = x*nw[d], output scaled by rsqrt in the epilogue. No extra passes.
// PDL: first W batch prefetched BEFORE cudaGridDependencySynchronize.
// NOTE: thread pairs (tn=0/1) share td, so Sx2 is double-counted -> /(2D).
// =============================================================================
#define GEMV_ACC(wv, xv) \
        a0.x = fmaf(wv.x, xv.x, a0.x); a0.y = fmaf(wv.x, xv.y, a0.y); \
        a0.z = fmaf(wv.x, xv.z, a0.z); a0.w = fmaf(wv.x, xv.w, a0.w); \
        a1.x = fmaf(wv.y, xv.x, a1.x); a1.y = fmaf(wv.y, xv.y, a1.y); \
        a1.z = fmaf(wv.y, xv.z, a1.z); a1.w = fmaf(wv.y, xv.w, a1.w); \
        a2.x = fmaf(wv.z, xv.x, a2.x); a2.y = fmaf(wv.z, xv.y, a2.y); \
        a2.z = fmaf(wv.z, xv.z, a2.z); a2.w = fmaf(wv.z, xv.w, a2.w); \
        a3.x = fmaf(wv.w, xv.x, a3.x); a3.y = fmaf(wv.w, xv.y, a3.y); \
        a3.z = fmaf(wv.w, xv.z, a3.z); a3.w = fmaf(wv.w, xv.w, a3.w);

#define SHFL16(o) \
        a0.x += __shfl_xor_sync(~0u, a0.x, o); a0.y += __shfl_xor_sync(~0u, a0.y, o); \
        a0.z += __shfl_xor_sync(~0u, a0.z, o); a0.w += __shfl_xor_sync(~0u, a0.w, o); \
        a1.x += __shfl_xor_sync(~0u, a1.x, o); a1.y += __shfl_xor_sync(~0u, a1.y, o); \
        a1.z += __shfl_xor_sync(~0u, a1.z, o); a1.w += __shfl_xor_sync(~0u, a1.w, o); \
        a2.x += __shfl_xor_sync(~0u, a2.x, o); a2.y += __shfl_xor_sync(~0u, a2.y, o); \
        a2.z += __shfl_xor_sync(~0u, a2.z, o); a2.w += __shfl_xor_sync(~0u, a2.w, o); \
        a3.x += __shfl_xor_sync(~0u, a3.x, o); a3.y += __shfl_xor_sync(~0u, a3.y, o); \
        a3.z += __shfl_xor_sync(~0u, a3.z, o); a3.w += __shfl_xor_sync(~0u, a3.w, o);

#define SS_ACC(xv) \
        ss.x = fmaf(xv.x, xv.x, ss.x); ss.y = fmaf(xv.y, xv.y, ss.y); \
        ss.z = fmaf(xv.z, xv.z, ss.z); ss.w = fmaf(xv.w, xv.w, ss.w);

#define NORM_SCALE(xv, wd) \
        xv.x *= wd; xv.y *= wd; xv.z *= wd; xv.w *= wd;

template<int D, bool NORM>
__device__ __forceinline__ void gemv8_core(
    const float* __restrict__ x, const float* __restrict__ nw,
    const float* __restrict__ W, int N, int n0,
    float* __restrict__ smrow /* [16][17] */, float4* __restrict__ sss /* [8] */) {
    int tid = threadIdx.x;
    int tn = tid & 1, td = tid >> 1, w = tid >> 5, lane = tid & 31;
    const float* Wp = W + n0 + tn*4 + (size_t)td*N;
    const float* xp = x + td*Bb;
    float4 a0 = {0,0,0,0}, a1 = a0, a2 = a0, a3 = a0;
    float4 ss = {0,0,0,0};
    constexpr int ITER = D / 128;   // 16 (D=2048) or 64 (D=8192)
    // ---- PDL prolog: first W batch is predecessor-independent ----
    float4 pw0 = __ldcs((const float4*)(Wp + (size_t)0*128*N));
    float4 pw1 = __ldcs((const float4*)(Wp + (size_t)1*128*N));
    float4 pw2 = __ldcs((const float4*)(Wp + (size_t)2*128*N));
    float4 pw3 = __ldcs((const float4*)(Wp + (size_t)3*128*N));
    float4 pw4 = __ldcs((const float4*)(Wp + (size_t)4*128*N));
    float4 pw5 = __ldcs((const float4*)(Wp + (size_t)5*128*N));
    float4 pw6 = __ldcs((const float4*)(Wp + (size_t)6*128*N));
    float4 pw7 = __ldcs((const float4*)(Wp + (size_t)7*128*N));
    cudaGridDependencySynchronize();
    #pragma unroll
    for (int i = 0; i < ITER; i += 8) {
        float4 wv0 = (i == 0) ? pw0 : __ldcs((const float4*)(Wp + (size_t)(i+0)*128*N));
        float4 wv1 = (i == 0) ? pw1 : __ldcs((const float4*)(Wp + (size_t)(i+1)*128*N));
        float4 wv2 = (i == 0) ? pw2 : __ldcs((const float4*)(Wp + (size_t)(i+2)*128*N));
        float4 wv3 = (i == 0) ? pw3 : __ldcs((const float4*)(Wp + (size_t)(i+3)*128*N));
        float4 wv4 = (i == 0) ? pw4 : __ldcs((const float4*)(Wp + (size_t)(i+4)*128*N));
        float4 wv5 = (i == 0) ? pw5 : __ldcs((const float4*)(Wp + (size_t)(i+5)*128*N));
        float4 wv6 = (i == 0) ? pw6 : __ldcs((const float4*)(Wp + (size_t)(i+6)*128*N));
        float4 wv7 = (i == 0) ? pw7 : __ldcs((const float4*)(Wp + (size_t)(i+7)*128*N));
        float4 xv0 = *(const float4*)(xp + (size_t)(i+0)*128*Bb);
        float4 xv1 = *(const float4*)(xp + (size_t)(i+1)*128*Bb);
        float4 xv2 = *(const float4*)(xp + (size_t)(i+2)*128*Bb);
        float4 xv3 = *(const float4*)(xp + (size_t)(i+3)*128*Bb);
        float4 xv4 = *(const float4*)(xp + (size_t)(i+4)*128*Bb);
        float4 xv5 = *(const float4*)(xp + (size_t)(i+5)*128*Bb);
        float4 xv6 = *(const float4*)(xp + (size_t)(i+6)*128*Bb);
        float4 xv7 = *(const float4*)(xp + (size_t)(i+7)*128*Bb);
        if (NORM) {
            float wd0 = nw[td + (i+0)*128], wd1 = nw[td + (i+1)*128];
            float wd2 = nw[td + (i+2)*128], wd3 = nw[td + (i+3)*128];
            float wd4 = nw[td + (i+4)*128], wd5 = nw[td + (i+5)*128];
            float wd6 = nw[td + (i+6)*128], wd7 = nw[td + (i+7)*128];
            SS_ACC(xv0) SS_ACC(xv1) SS_ACC(xv2) SS_ACC(xv3)
            SS_ACC(xv4) SS_ACC(xv5) SS_ACC(xv6) SS_ACC(xv7)
            NORM_SCALE(xv0, wd0) NORM_SCALE(xv1, wd1)
            NORM_SCALE(xv2, wd2) NORM_SCALE(xv3, wd3)
            NORM_SCALE(xv4, wd4) NORM_SCALE(xv5, wd5)
            NORM_SCALE(xv6, wd6) NORM_SCALE(xv7, wd7)
        }
        GEMV_ACC(wv0, xv0)
        GEMV_ACC(wv1, xv1)
        GEMV_ACC(wv2, xv2)
        GEMV_ACC(wv3, xv3)
        GEMV_ACC(wv4, xv4)
        GEMV_ACC(wv5, xv5)
        GEMV_ACC(wv6, xv6)
        GEMV_ACC(wv7, xv7)
    }
    SHFL16(16) SHFL16(8) SHFL16(4) SHFL16(2)
    if (NORM) {
        #pragma unroll
        for (int o = 16; o; o >>= 1) {
            ss.x += __shfl_xor_sync(~0u, ss.x, o); ss.y += __shfl_xor_sync(~0u, ss.y, o);
            ss.z += __shfl_xor_sync(~0u, ss.z, o); ss.w += __shfl_xor_sync(~0u, ss.w, o);
        }
        if (lane == 0) sss[w] = ss;
    }
    if (lane < 2) {
        float* s = smrow + (w*2 + tn)*17;
        s[0]=a0.x; s[1]=a0.y; s[2]=a0.z; s[3]=a0.w;
        s[4]=a1.x; s[5]=a1.y; s[6]=a1.z; s[7]=a1.w;
        s[8]=a2.x; s[9]=a2.y; s[10]=a2.z; s[11]=a2.w;
        s[12]=a3.x; s[13]=a3.y; s[14]=a3.z; s[15]=a3.w;
    }
}

// epilogue helper: compute per-batch rsqrt factors from sss (double-counted)
template<int D>
__device__ __forceinline__ float4 norm_from_sss(const float4* sss) {
    float4 t = {0,0,0,0};
    #pragma unroll
    for (int i = 0; i < 8; i++) {
        t.x += sss[i].x; t.y += sss[i].y; t.z += sss[i].z; t.w += sss[i].w;
    }
    float dinv = 1.0f / (2.0f * (float)D);   // pairs double-count
    float4 r = { rsqrtf(t.x*dinv + EPS), rsqrtf(t.y*dinv + EPS),
                 rsqrtf(t.z*dinv + EPS), rsqrtf(t.w*dinv + EPS) };
    return r;
}

template<int D, bool RES, bool OUTBN, bool NORM>
__global__ void __launch_bounds__(256) gemv8_k(
    const float* __restrict__ x, const float* __restrict__ nw,
    const float* __restrict__ W, float* __restrict__ y, int N) {
    __shared__ float sred[16*17];
    __shared__ float4 sss[8];
    int n0 = blockIdx.x * 8;
    gemv8_core<D, NORM>(x, nw, W, N, n0, sred, sss);
    __syncthreads();
    int tid = threadIdx.x;
    if (tid < 32) {
        float4 r = {1,1,1,1};
        if (NORM) r = norm_from_sss<D>(sss);
        int tno = tid >> 4, j = tid & 15;
        float s = 0.f;
        #pragma unroll
        for (int ww = 0; ww < 8; ww++) s += sred[(ww*2 + tno)*17 + j];
        int c = j >> 2, b = j & 3;
        int n = n0 + tno*4 + c;
        if (NORM) s *= sel4(r, b);
        if (OUTBN) {
            y[(size_t)b*N + n] = s;
        } else {
            if (RES) s += y[n*Bb + b];
            y[n*Bb + b] = s;
        }
    }
}

// fused ln1-rmsnorm + q/k/v projection: one launch, 512 blocks
__global__ void __launch_bounds__(256) gemv8_qkv_k(
    const float* __restrict__ x, const float* __restrict__ nw,
    const float* __restrict__ wq, const float* __restrict__ wk,
    const float* __restrict__ wv, float* __restrict__ qkv) {
    __shared__ float sred[16*17];
    __shared__ float4 sss[8];
    int nb = blockIdx.x;
    const float* W; float* y; int N, n0;
    if (nb < 256)      { W = wq; y = qkv;           N = 2048; n0 = nb*8; }
    else if (nb < 384) { W = wk; y = qkv + 2048*Bb; N = 1024; n0 = (nb-256)*8; }
    else               { W = wv; y = qkv + 3072*Bb; N = 1024; n0 = (nb-384)*8; }
    gemv8_core<Dm, true>(x, nw, W, N, n0, sred, sss);
    __syncthreads();
    int tid = threadIdx.x;
    if (tid < 32) {
        float4 r = norm_from_sss<Dm>(sss);
        int tno = tid >> 4, j = tid & 15;
        float s = 0.f;
        #pragma unroll
        for (int ww = 0; ww < 8; ww++) s += sred[(ww*2 + tno)*17 + j];
        int c = j >> 2, b = j & 3;
        int n = n0 + tno*4 + c;
        y[n*Bb + b] = s * sel4(r, b);
    }
}

// fused ln2-rmsnorm + gate/up GEMV + silu(g)*u -> 1024 blocks
__global__ void __launch_bounds__(256) gemv8_gateup_k(
    const float* __restrict__ x, const float* __restrict__ nw,
    const float* __restrict__ Wg, const float* __restrict__ Wu,
    float* __restrict__ y, int N) {
    __shared__ float sred[16*33];
    __shared__ float4 sss[8];
    int tid = threadIdx.x;
    int tn = tid & 1, td = tid >> 1, w = tid >> 5, lane = tid & 31;
    int n0 = blockIdx.x * 8;
    const float* Wgp = Wg + n0 + tn*4 + (size_t)td*N;
    const float* Wup = Wu + n0 + tn*4 + (size_t)td*N;
    const float* xp = x + td*Bb;
    float4 ga0 = {0,0,0,0}, ga1 = ga0, ga2 = ga0, ga3 = ga0;
    float4 ua0 = ga0, ua1 = ga0, ua2 = ga0, ua3 = ga0;
    float4 ss = {0,0,0,0};
    constexpr int ITER = Dm / 128;
    // ---- PDL prolog ----
    float4 pg0 = __ldcs((const float4*)(Wgp + (size_t)0*128*N));
    float4 pg1 = __ldcs((const float4*)(Wgp + (size_t)1*128*N));
    float4 pg2 = __ldcs((const float4*)(Wgp + (size_t)2*128*N));
    float4 pg3 = __ldcs((const float4*)(Wgp + (size_t)3*128*N));
    float4 pu0 = __ldcs((const float4*)(Wup + (size_t)0*128*N));
    float4 pu1 = __ldcs((const float4*)(Wup + (size_t)1*128*N));
    float4 pu2 = __ldcs((const float4*)(Wup + (size_t)2*128*N));
    float4 pu3 = __ldcs((const float4*)(Wup + (size_t)3*128*N));
    cudaGridDependencySynchronize();
    #pragma unroll
    for (int i = 0; i < ITER; i += 4) {
        float4 wg0 = (i == 0) ? pg0 : __ldcs((const float4*)(Wgp + (size_t)(i+0)*128*N));
        float4 wg1 = (i == 0) ? pg1 : __ldcs((const float4*)(Wgp + (size_t)(i+1)*128*N));
        float4 wg2 = (i == 0) ? pg2 : __ldcs((const float4*)(Wgp + (size_t)(i+2)*128*N));
        float4 wg3 = (i == 0) ? pg3 : __ldcs((const float4*)(Wgp + (size_t)(i+3)*128*N));
        float4 wu0 = (i == 0) ? pu0 : __ldcs((const float4*)(Wup + (size_t)(i+0)*128*N));
        float4 wu1 = (i == 0) ? pu1 : __ldcs((const float4*)(Wup + (size_t)(i+1)*128*N));
        float4 wu2 = (i == 0) ? pu2 : __ldcs((const float4*)(Wup + (size_t)(i+2)*128*N));
        float4 wu3 = (i == 0) ? pu3 : __ldcs((const float4*)(Wup + (size_t)(i+3)*128*N));
        float4 xv0 = *(const float4*)(xp + (size_t)(i+0)*128*Bb);
        float4 xv1 = *(const float4*)(xp + (size_t)(i+1)*128*Bb);
        float4 xv2 = *(const float4*)(xp + (size_t)(i+2)*128*Bb);
        float4 xv3 = *(const float4*)(xp + (size_t)(i+3)*128*Bb);
        float wd0 = nw[td + (i+0)*128], wd1 = nw[td + (i+1)*128];
        float wd2 = nw[td + (i+2)*128], wd3 = nw[td + (i+3)*128];
        SS_ACC(xv0) SS_ACC(xv1) SS_ACC(xv2) SS_ACC(xv3)
        NORM_SCALE(xv0, wd0) NORM_SCALE(xv1, wd1)
        NORM_SCALE(xv2, wd2) NORM_SCALE(xv3, wd3)
        {
            float4 &a0 = ga0, &a1 = ga1, &a2 = ga2, &a3 = ga3;
            GEMV_ACC(wg0, xv0)
            GEMV_ACC(wg1, xv1)
            GEMV_ACC(wg2, xv2)
            GEMV_ACC(wg3, xv3)
        }
        {
            float4 &a0 = ua0, &a1 = ua1, &a2 = ua2, &a3 = ua3;
            GEMV_ACC(wu0, xv0)
            GEMV_ACC(wu1, xv1)
            GEMV_ACC(wu2, xv2)
            GEMV_ACC(wu3, xv3)
        }
    }
    {
        float4 &a0 = ga0, &a1 = ga1, &a2 = ga2, &a3 = ga3;
        SHFL16(16) SHFL16(8) SHFL16(4) SHFL16(2)
    }
    {
        float4 &a0 = ua0, &a1 = ua1, &a2 = ua2, &a3 = ua3;
        SHFL16(16) SHFL16(8) SHFL16(4) SHFL16(2)
    }
    #pragma unroll
    for (int o = 16; o; o >>= 1) {
        ss.x += __shfl_xor_sync(~0u, ss.x, o); ss.y += __shfl_xor_sync(~0u, ss.y, o);
        ss.z += __shfl_xor_sync(~0u, ss.z, o); ss.w += __shfl_xor_sync(~0u, ss.w, o);
    }
    if (lane == 0) sss[w] = ss;
    if (lane < 2) {
        float* s = &sred[(w*2 + tn)*33];
        s[0]=ga0.x; s[1]=ga0.y; s[2]=ga0.z; s[3]=ga0.w;
        s[4]=ga1.x; s[5]=ga1.y; s[6]=ga1.z; s[7]=ga1.w;
        s[8]=ga2.x; s[9]=ga2.y; s[10]=ga2.z; s[11]=ga2.w;
        s[12]=ga3.x; s[13]=ga3.y; s[14]=ga3.z; s[15]=ga3.w;
        s[16]=ua0.x; s[17]=ua0.y; s[18]=ua0.z; s[19]=ua0.w;
        s[20]=ua1.x; s[21]=ua1.y; s[22]=ua1.z; s[23]=ua1.w;
        s[24]=ua2.x; s[25]=ua2.y; s[26]=ua2.z; s[27]=ua2.w;
        s[28]=ua3.x; s[29]=ua3.y; s[30]=ua3.z; s[31]=ua3.w;
    }
    __syncthreads();
    if (tid < 32) {
        float4 r = norm_from_sss<Dm>(sss);
        int tno = tid >> 4, j = tid & 15;
        float sg = 0.f, su = 0.f;
        #pragma unroll
        for (int ww = 0; ww < 8; ww++) {
            sg += sred[(ww*2 + tno)*33 + j];
            su += sred[(ww*2 + tno)*33 + 16 + j];
        }
        int c = j >> 2, b = j & 3;
        int n = n0 + tno*4 + c;
        float rb = sel4(r, b);
        sg *= rb; su *= rb;
        float silu = sg / (1.f + __expf(-sg));
        y[n*Bb + b] = silu * su;
    }
}

// ---------------- fused rope + flash-decode attention ------------------------
__device__ __forceinline__ float dot4(float4 a, float4 b) {
    return a.x*b.x + a.y*b.y + a.z*b.z + a.w*b.w;
}

__global__ void __launch_bounds__(128) attn2_k(
    const float* __restrict__ kc, const float* __restrict__ vc,
    const int* __restrict__ cpos, const float* __restrict__ qkv,
    const float* __restrict__ qnw, const float* __restrict__ knw,
    float* __restrict__ pacc, float* __restrict__ pm, float* __restrict__ pl) {
    cudaGridDependencySynchronize();
    int bkv = blockIdx.x, chunk = blockIdx.y;
    int b = bkv >> 3, kv = bkv & 7;
    int t = threadIdx.x, w = t >> 5, lane = t & 31;
    int P = cpos[0];
    int n = P + 1;
    int csz = (n + NCHUNK - 1) / NCHUNK;
    int start = chunk * csz;
    int end = min(start + csz, n);
    int bh0 = b*Hh + kv*2;
    if (start >= n) {   // empty chunk (only when n < NCHUNK)
        for (int i = t; i < 2*HD; i += 128) {
            int hh = i >> 7, tt = i & 127;
            pacc[((size_t)(bh0 + hh)*NCHUNK + chunk)*HD + tt] = 0.f;
        }
        if (t < 2) {
            pm[(bh0 + t)*NCHUNK + chunk] = -1e30f;
            pl[(bh0 + t)*NCHUNK + chunk] = 0.f;
        }
        return;
    }

    // ---- inline per-head rmsnorm + rope of q0,q1,k (and v passthrough) ----
    float q0 = qkv[((kv*2    )*HD + t)*Bb + b];
    float q1 = qkv[((kv*2 + 1)*HD + t)*Bb + b];
    float kkv = qkv[(2048 + kv*HD + t)*Bb + b];
    float vvv = qkv[(3072 + kv*HD + t)*Bb + b];
    __shared__ float red[3][4];
    float s0 = q0*q0, s1 = q1*q1, s2 = kkv*kkv;
    #pragma unroll
    for (int o = 16; o; o >>= 1) {
        s0 += __shfl_xor_sync(~0u, s0, o);
        s1 += __shfl_xor_sync(~0u, s1, o);
        s2 += __shfl_xor_sync(~0u, s2, o);
    }
    if (lane == 0) { red[0][w] = s0; red[1][w] = s1; red[2][w] = s2; }
    __syncthreads();
    float r0 = rsqrtf((red[0][0]+red[0][1]+red[0][2]+red[0][3])/(float)HD + EPS);
    float r1 = rsqrtf((red[1][0]+red[1][1]+red[1][2]+red[1][3])/(float)HD + EPS);
    float r2 = rsqrtf((red[2][0]+red[2][1]+red[2][2]+red[2][3])/(float)HD + EPS);
    float qw_ = qnw[t], kw_ = knw[t];
    q0 *= r0*qw_; q1 *= r1*qw_; kkv *= r2*kw_;
    __shared__ __align__(16) float sq0[HD], sq1[HD], sk[HD], sv[HD];
    sq0[t] = q0; sq1[t] = q1; sk[t] = kkv;
    __syncthreads();
    {
        int i = t & 63;
        float inv = __expf(-(float)i * ROPE_C);
        float ang = (float)P * inv;
        float sn, cs;
        __sincosf(ang, &sn, &cs);
        float o0, o1, ok;
        if (t < 64) { o0 = q0*cs - sq0[t+64]*sn; o1 = q1*cs - sq1[t+64]*sn; ok = kkv*cs - sk[t+64]*sn; }
        else        { o0 = q0*cs + sq0[t-64]*sn; o1 = q1*cs + sq1[t-64]*sn; ok = kkv*cs + sk[t-64]*sn; }
        __syncthreads();
        sq0[t] = o0; sq1[t] = o1; sk[t] = ok; sv[t] = vvv;
    }
    __syncthreads();

    // ---- flash-decode over this chunk (scale folded into q) ----
    float4 qf0 = *(const float4*)(sq0 + lane*4);
    float4 qf1 = *(const float4*)(sq1 + lane*4);
    qf0.x *= ATT_SCALE; qf0.y *= ATT_SCALE; qf0.z *= ATT_SCALE; qf0.w *= ATT_SCALE;
    qf1.x *= ATT_SCALE; qf1.y *= ATT_SCALE; qf1.z *= ATT_SCALE; qf1.w *= ATT_SCALE;
    const float* Kbase = kc + ((size_t)b*KVh + kv)*MAXP*HD;
    const float* Vbase = vc + ((size_t)b*KVh + kv)*MAXP*HD;
    float m0 = -1e30f, m1 = -1e30f, l0 = 0.f, l1 = 0.f;
    float4 a0 = {0,0,0,0}, a1 = a0;
    int endEx = min(end, P);   // exclusive of new-token position P
    int p = start + w;
    // ---- main: 2 positions per warp-iteration (p and p+4), fused update ----
    for (; p + 4 < endEx; p += 8) {
        float4 ka = __ldcs((const float4*)(Kbase + (size_t)p*HD) + lane);
        float4 kb = __ldcs((const float4*)(Kbase + (size_t)(p+4)*HD) + lane);
        float4 va = __ldcs((const float4*)(Vbase + (size_t)p*HD) + lane);
        float4 vb = __ldcs((const float4*)(Vbase + (size_t)(p+4)*HD) + lane);
        float d0a = dot4(qf0, ka), d1a = dot4(qf1, ka);
        float d0b = dot4(qf0, kb), d1b = dot4(qf1, kb);
        #pragma unroll
        for (int o = 16; o; o >>= 1) {
            d0a += __shfl_xor_sync(~0u, d0a, o);
            d1a += __shfl_xor_sync(~0u, d1a, o);
            d0b += __shfl_xor_sync(~0u, d0b, o);
            d1b += __shfl_xor_sync(~0u, d1b, o);
        }
        {
            float mn = fmaxf(m0, fmaxf(d0a, d0b));
            float c  = __expf(m0 - mn);
            float pa = __expf(d0a - mn), pb = __expf(d0b - mn);
            l0 = l0*c + pa + pb;
            a0.x = a0.x*c + pa*va.x + pb*vb.x;
            a0.y = a0.y*c + pa*va.y + pb*vb.y;
            a0.z = a0.z*c + pa*va.z + pb*vb.z;
            a0.w = a0.w*c + pa*va.w + pb*vb.w;
            m0 = mn;
        }
        {
            float mn = fmaxf(m1, fmaxf(d1a, d1b));
            float c  = __expf(m1 - mn);
            float pa = __expf(d1a - mn), pb = __expf(d1b - mn);
            l1 = l1*c + pa + pb;
            a1.x = a1.x*c + pa*va.x + pb*vb.x;
            a1.y = a1.y*c + pa*va.y + pb*vb.y;
            a1.z = a1.z*c + pa*va.z + pb*vb.z;
            a1.w = a1.w*c + pa*va.w + pb*vb.w;
            m1 = mn;
        }
    }
    // ---- tail: single position ----
    for (; p < endEx; p += 4) {
        float4 kk = __ldcs((const float4*)(Kbase + (size_t)p*HD) + lane);
        float4 vv = __ldcs((const float4*)(Vbase + (size_t)p*HD) + lane);
        float d0 = dot4(qf0, kk), d1 = dot4(qf1, kk);
        #pragma unroll
        for (int o = 16; o; o >>= 1) {
            d0 += __shfl_xor_sync(~0u, d0, o);
            d1 += __shfl_xor_sync(~0u, d1, o);
        }
        float mn0 = fmaxf(m0, d0), c0 = __expf(m0 - mn0), p0 = __expf(d0 - mn0);
        l0 = l0*c0 + p0;
        a0.x = a0.x*c0 + p0*vv.x; a0.y = a0.y*c0 + p0*vv.y;
        a0.z = a0.z*c0 + p0*vv.z; a0.w = a0.w*c0 + p0*vv.w;
        m0 = mn0;
        float mn1 = fmaxf(m1, d1), c1 = __expf(m1 - mn1), p1 = __expf(d1 - mn1);
        l1 = l1*c1 + p1;
        a1.x = a1.x*c1 + p1*vv.x; a1.y = a1.y*c1 + p1*vv.y;
        a1.z = a1.z*c1 + p1*vv.z; a1.w = a1.w*c1 + p1*vv.w;
        m1 = mn1;
    }
    // ---- new-token position P (from shared), if in this chunk ----
    if (P >= start && P < end && w == ((P - start) & 3)) {
        float4 kk = *(const float4*)(sk + lane*4);
        float4 vv = *(const float4*)(sv + lane*4);
        float d0 = dot4(qf0, kk), d1 = dot4(qf1, kk);
        #pragma unroll
        for (int o = 16; o; o >>= 1) {
            d0 += __shfl_xor_sync(~0u, d0, o);
            d1 += __shfl_xor_sync(~0u, d1, o);
        }
        float mn0 = fmaxf(m0, d0), c0 = __expf(m0 - mn0), p0 = __expf(d0 - mn0);
        l0 = l0*c0 + p0;
        a0.x = a0.x*c0 + p0*vv.x; a0.y = a0.y*c0 + p0*vv.y;
        a0.z = a0.z*c0 + p0*vv.z; a0.w = a0.w*c0 + p0*vv.w;
        m0 = mn0;
        float mn1 = fmaxf(m1, d1), c1 = __expf(m1 - mn1), p1 = __expf(d1 - mn1);
        l1 = l1*c1 + p1;
        a1.x = a1.x*c1 + p1*vv.x; a1.y = a1.y*c1 + p1*vv.y;
        a1.z = a1.z*c1 + p1*vv.z; a1.w = a1.w*c1 + p1*vv.w;
        m1 = mn1;
    }

    __shared__ float sm_m[2][4], sm_l[2][4];
    __shared__ float sm_a[2][4][HD];
    if (lane == 0) { sm_m[0][w] = m0; sm_l[0][w] = l0; sm_m[1][w] = m1; sm_l[1][w] = l1; }
    *(float4*)&sm_a[0][w][lane*4] = a0;
    *(float4*)&sm_a[1][w][lane*4] = a1;
    __syncthreads();
    #pragma unroll
    for (int hh = 0; hh < 2; hh++) {
        float M = fmaxf(fmaxf(sm_m[hh][0], sm_m[hh][1]), fmaxf(sm_m[hh][2], sm_m[hh][3]));
        float L = 0.f, A = 0.f;
        #pragma unroll
        for (int ww = 0; ww < 4; ww++) {
            float e = __expf(sm_m[hh][ww] - M);
            L += sm_l[hh][ww] * e;
            A += sm_a[hh][ww][t] * e;
        }
        pacc[((size_t)(bh0 + hh)*NCHUNK + chunk)*HD + t] = A;
        if (t == 0) {
            pm[(bh0 + hh)*NCHUNK + chunk] = M;
            pl[(bh0 + hh)*NCHUNK + chunk] = L;
        }
    }
}

__global__ void attn_comb_k(const float* __restrict__ pacc, const float* __restrict__ pm,
                            const float* __restrict__ pl, float* __restrict__ o) {
    cudaGridDependencySynchronize();
    int bh = blockIdx.x, t = threadIdx.x;
    int b = bh / Hh, h = bh % Hh;
    float M = -1e30f;
    #pragma unroll
    for (int c = 0; c < NCHUNK; c++) M = fmaxf(M, pm[bh*NCHUNK + c]);
    float L = 0.f, A = 0.f;
    #pragma unroll
    for (int c = 0; c < NCHUNK; c++) {
        float e = __expf(pm[bh*NCHUNK + c] - M);
        L += pl[bh*NCHUNK + c] * e;
        A += pacc[((size_t)bh*NCHUNK + c)*HD + t] * e;
    }
    o[(h*HD + t)*Bb + b] = A / L;
}

// ---------------- PDL launch helper ------------------------------------------
template <typename... Args, typename... Ts>
static void pdl_launch(void (*kern)(Args...), dim3 grid, dim3 block, Ts... args) {
    cudaLaunchConfig_t cfg = {};
    cfg.gridDim = grid;
    cfg.blockDim = block;
    cfg.dynamicSmemBytes = 0;
    cfg.stream = 0;
    cudaLaunchAttribute at[1];
    at[0].id = cudaLaunchAttributeProgrammaticStreamSerialization;
    at[0].val.programmaticStreamSerializationAllowed = 1;
    cfg.attrs = at;
    cfg.numAttrs = 1;
    cudaLaunchKernelEx(&cfg, kern, static_cast<Args>(args)...);
}

// ---------------- host orchestration ----------------------------------------
extern "C" void kernel_launch(void* const* d_in, const int* in_sizes, int n_in,
                              void* d_out, int out_size) {
    const int*   tok    = (const int*)  d_in[0];
    const int*   cpos   = (const int*)  d_in[1];
    const float* kcache = (const float*)d_in[2];
    const float* vcache = (const float*)d_in[3];
    const float* embw   = (const float*)d_in[4];
    const float* ln1    = (const float*)d_in[5];
    const float* wq     = (const float*)d_in[6];
    const float* wk     = (const float*)d_in[7];
    const float* wv     = (const float*)d_in[8];
    const float* qnw    = (const float*)d_in[9];
    const float* knw    = (const float*)d_in[10];
    const float* wo     = (const float*)d_in[11];
    const float* ln2    = (const float*)d_in[12];
    const float* wg     = (const float*)d_in[13];
    const float* wu     = (const float*)d_in[14];
    const float* wd     = (const float*)d_in[15];
    const float* fnw    = (const float*)d_in[16];
    const float* lmw    = (const float*)d_in[17];
    float* out = (float*)d_out;

    float *x, *qkv, *o, *g, *pacc, *pm, *pl;
    cudaGetSymbolAddress((void**)&x,    g_x);
    cudaGetSymbolAddress((void**)&qkv,  g_qkv);
    cudaGetSymbolAddress((void**)&o,    g_o);
    cudaGetSymbolAddress((void**)&g,    g_g);
    cudaGetSymbolAddress((void**)&pacc, g_pacc);
    cudaGetSymbolAddress((void**)&pm,   g_pm);
    cudaGetSymbolAddress((void**)&pl,   g_pl);

    pdl_launch(embed_k, dim3(Dm/256, Bb), dim3(256), tok, embw, x);

    for (int l = 0; l < Ll; l++) {
        const float* wq_l = wq + (size_t)l*Dm*Hh*HD;
        const float* wk_l = wk + (size_t)l*Dm*KVh*HD;
        const float* wv_l = wv + (size_t)l*Dm*KVh*HD;
        const float* wo_l = wo + (size_t)l*Hh*HD*Dm;
        const float* wg_l = wg + (size_t)l*Dm*Ff;
        const float* wu_l = wu + (size_t)l*Dm*Ff;
        const float* wd_l = wd + (size_t)l*Ff*Dm;
        const float* kc_l = kcache + (size_t)l*Bb*KVh*MAXP*HD;
        const float* vc_l = vcache + (size_t)l*Bb*KVh*MAXP*HD;

        pdl_launch(gemv8_qkv_k, dim3(512), dim3(256), x, ln1 + l*Dm, wq_l, wk_l, wv_l, qkv);
        pdl_launch(attn2_k, dim3(Bb*KVh, NCHUNK), dim3(128), kc_l, vc_l, cpos, qkv,
                   qnw + l*HD, knw + l*HD, pacc, pm, pl);
        pdl_launch(attn_comb_k, dim3(Bb*Hh), dim3(HD), pacc, pm, pl, o);
        pdl_launch(gemv8_k<Dm, true, false, false>, dim3(256), dim3(256),
                   o, (const float*)nullptr, wo_l, x, 2048);
        pdl_launch(gemv8_gateup_k, dim3(Ff/8), dim3(256), x, ln2 + l*Dm, wg_l, wu_l, g, Ff);
        pdl_launch(gemv8_k<Ff, true, false, false>, dim3(256), dim3(256),
                   g, (const float*)nullptr, wd_l, x, 2048);
    }

    pdl_launch(gemv8_k<Dm, false, true, true>, dim3(Vv/8), dim3(256),
               x, fnw, lmw, out, Vv);
}

// round 11
// speedup vs baseline: 1.4012x; 1.4012x over previous
#include <cuda_runtime.h>
#include <math.h>

#define Dm   2048
#define Hh   16
#define KVh  8
#define HD   128
#define Ff   8192
#define Vv   32000
#define MAXP 4096
#define Bb   4
#define Ll   2
#define EPS  1e-6f
#define ATT_SCALE 0.08838834764831845f   // 1/sqrt(128)
#define NCHUNK 32
#define ROPE_C 0.21586735f                // ln(1e6)/64

// ---------------- scratch (allocation-free: __device__ globals) -------------
__device__ __align__(16) float g_x  [Dm*Bb];        // residual ping, [D][B]
__device__ __align__(16) float g_x2 [Dm*Bb];        // residual pong, [D][B]
__device__ __align__(16) float g_h  [Dm*Bb];        // normalized, [D][B]
__device__ __align__(16) float g_qkv[4096*Bb];      // q|k|v, [N][B]
__device__ __align__(16) float g_o  [Dm*Bb];        // attn out, [N][B]
__device__ __align__(16) float g_g  [Ff*Bb];        // mlp mid, [F][B]
__device__ __align__(16) float g_part[2*Dm*Bb];     // split-K partials [2][D][B]
__device__ __align__(16) float g_pacc[Bb*Hh*NCHUNK*HD];
__device__ float g_pm[Bb*Hh*NCHUNK];
__device__ float g_pl[Bb*Hh*NCHUNK];

// ---------------- fused embed + rmsnorm (layer 0) ----------------------------
__global__ void __launch_bounds__(256) rms_embed_k(
    const int* __restrict__ tok, const float* __restrict__ emb,
    const float* __restrict__ w, float* __restrict__ x, float* __restrict__ h) {
    cudaGridDependencySynchronize();
    __shared__ float4 snorm[8];
    int tid = threadIdx.x, wp = tid >> 5, lane = tid & 31;
    const float* e0 = emb + (size_t)tok[0]*Dm;
    const float* e1 = emb + (size_t)tok[1]*Dm;
    const float* e2 = emb + (size_t)tok[2]*Dm;
    const float* e3 = emb + (size_t)tok[3]*Dm;
    float4 ss = {0,0,0,0};
    for (int d = tid; d < Dm; d += 256) {
        float v0 = e0[d], v1 = e1[d], v2 = e2[d], v3 = e3[d];
        ss.x = fmaf(v0, v0, ss.x); ss.y = fmaf(v1, v1, ss.y);
        ss.z = fmaf(v2, v2, ss.z); ss.w = fmaf(v3, v3, ss.w);
    }
    #pragma unroll
    for (int o = 16; o; o >>= 1) {
        ss.x += __shfl_xor_sync(~0u, ss.x, o); ss.y += __shfl_xor_sync(~0u, ss.y, o);
        ss.z += __shfl_xor_sync(~0u, ss.z, o); ss.w += __shfl_xor_sync(~0u, ss.w, o);
    }
    if (lane == 0) snorm[wp] = ss;
    __syncthreads();
    float4 t = {0,0,0,0};
    #pragma unroll
    for (int i = 0; i < 8; i++) {
        t.x += snorm[i].x; t.y += snorm[i].y; t.z += snorm[i].z; t.w += snorm[i].w;
    }
    float dinv = 1.0f / (float)Dm;
    float4 r = { rsqrtf(t.x*dinv + EPS), rsqrtf(t.y*dinv + EPS),
                 rsqrtf(t.z*dinv + EPS), rsqrtf(t.w*dinv + EPS) };
    int seg = Dm / gridDim.x;
    int d0 = blockIdx.x * seg;
    for (int d = d0 + tid; d < d0 + seg; d += 256) {
        float4 xv = { e0[d], e1[d], e2[d], e3[d] };
        *(float4*)(x + d*Bb) = xv;
        float wd = w[d];
        float4 ov = { xv.x*r.x*wd, xv.y*r.y*wd, xv.z*r.z*wd, xv.w*r.w*wd };
        *(float4*)(h + d*Bb) = ov;
    }
}

// ---------------- fused split-K combine + residual add + rmsnorm -------------
// xout = xin + part[0] + part[1]; h = norm(xout)*w.  xout != xin (ping-pong).
__global__ void __launch_bounds__(256) rms_add_k(
    const float* __restrict__ xin, const float* __restrict__ part,
    const float* __restrict__ w, float* __restrict__ xout,
    float* __restrict__ h) {
    cudaGridDependencySynchronize();
    __shared__ float4 snorm[8];
    int tid = threadIdx.x, wp = tid >> 5, lane = tid & 31;
    float4 ss = {0,0,0,0};
    for (int d = tid; d < Dm; d += 256) {
        float4 xv = *(const float4*)(xin + d*Bb);
        float4 p0 = *(const float4*)(part + d*Bb);
        float4 p1 = *(const float4*)(part + (Dm + d)*Bb);
        xv.x += p0.x + p1.x; xv.y += p0.y + p1.y;
        xv.z += p0.z + p1.z; xv.w += p0.w + p1.w;
        ss.x = fmaf(xv.x, xv.x, ss.x); ss.y = fmaf(xv.y, xv.y, ss.y);
        ss.z = fmaf(xv.z, xv.z, ss.z); ss.w = fmaf(xv.w, xv.w, ss.w);
    }
    #pragma unroll
    for (int o = 16; o; o >>= 1) {
        ss.x += __shfl_xor_sync(~0u, ss.x, o); ss.y += __shfl_xor_sync(~0u, ss.y, o);
        ss.z += __shfl_xor_sync(~0u, ss.z, o); ss.w += __shfl_xor_sync(~0u, ss.w, o);
    }
    if (lane == 0) snorm[wp] = ss;
    __syncthreads();
    float4 t = {0,0,0,0};
    #pragma unroll
    for (int i = 0; i < 8; i++) {
        t.x += snorm[i].x; t.y += snorm[i].y; t.z += snorm[i].z; t.w += snorm[i].w;
    }
    float dinv = 1.0f / (float)Dm;
    float4 r = { rsqrtf(t.x*dinv + EPS), rsqrtf(t.y*dinv + EPS),
                 rsqrtf(t.z*dinv + EPS), rsqrtf(t.w*dinv + EPS) };
    int seg = Dm / gridDim.x;
    int d0 = blockIdx.x * seg;
    for (int d = d0 + tid; d < d0 + seg; d += 256) {
        float4 xv = *(const float4*)(xin + d*Bb);
        float4 p0 = *(const float4*)(part + d*Bb);
        float4 p1 = *(const float4*)(part + (Dm + d)*Bb);
        xv.x += p0.x + p1.x; xv.y += p0.y + p1.y;
        xv.z += p0.z + p1.z; xv.w += p0.w + p1.w;
        *(float4*)(xout + d*Bb) = xv;
        float wd = w[d];
        float4 ov = { xv.x*r.x*wd, xv.y*r.y*wd, xv.z*r.z*wd, xv.w*r.w*wd };
        *(float4*)(h + d*Bb) = ov;
    }
}

// =============================================================================
// batch-4 GEMV core — R8/R9 proven shape: flat 8-deep batches + PDL W-prolog.
// =============================================================================
#define GEMV_ACC(wv, xv) \
        a0.x = fmaf(wv.x, xv.x, a0.x); a0.y = fmaf(wv.x, xv.y, a0.y); \
        a0.z = fmaf(wv.x, xv.z, a0.z); a0.w = fmaf(wv.x, xv.w, a0.w); \
        a1.x = fmaf(wv.y, xv.x, a1.x); a1.y = fmaf(wv.y, xv.y, a1.y); \
        a1.z = fmaf(wv.y, xv.z, a1.z); a1.w = fmaf(wv.y, xv.w, a1.w); \
        a2.x = fmaf(wv.z, xv.x, a2.x); a2.y = fmaf(wv.z, xv.y, a2.y); \
        a2.z = fmaf(wv.z, xv.z, a2.z); a2.w = fmaf(wv.z, xv.w, a2.w); \
        a3.x = fmaf(wv.w, xv.x, a3.x); a3.y = fmaf(wv.w, xv.y, a3.y); \
        a3.z = fmaf(wv.w, xv.z, a3.z); a3.w = fmaf(wv.w, xv.w, a3.w);

#define SHFL16(o) \
        a0.x += __shfl_xor_sync(~0u, a0.x, o); a0.y += __shfl_xor_sync(~0u, a0.y, o); \
        a0.z += __shfl_xor_sync(~0u, a0.z, o); a0.w += __shfl_xor_sync(~0u, a0.w, o); \
        a1.x += __shfl_xor_sync(~0u, a1.x, o); a1.y += __shfl_xor_sync(~0u, a1.y, o); \
        a1.z += __shfl_xor_sync(~0u, a1.z, o); a1.w += __shfl_xor_sync(~0u, a1.w, o); \
        a2.x += __shfl_xor_sync(~0u, a2.x, o); a2.y += __shfl_xor_sync(~0u, a2.y, o); \
        a2.z += __shfl_xor_sync(~0u, a2.z, o); a2.w += __shfl_xor_sync(~0u, a2.w, o); \
        a3.x += __shfl_xor_sync(~0u, a3.x, o); a3.y += __shfl_xor_sync(~0u, a3.y, o); \
        a3.z += __shfl_xor_sync(~0u, a3.z, o); a3.w += __shfl_xor_sync(~0u, a3.w, o);

template<int D>
__device__ __forceinline__ void gemv8_core(
    const float* __restrict__ x, const float* __restrict__ W,
    int N, int n0, float* __restrict__ smrow /* [16][17] */) {
    int tid = threadIdx.x;
    int tn = tid & 1, td = tid >> 1, w = tid >> 5, lane = tid & 31;
    const float* Wp = W + n0 + tn*4 + (size_t)td*N;
    const float* xp = x + td*Bb;
    float4 a0 = {0,0,0,0}, a1 = a0, a2 = a0, a3 = a0;
    constexpr int ITER = D / 128;
    // ---- PDL prolog: first W batch is predecessor-independent ----
    float4 pw0 = __ldcs((const float4*)(Wp + (size_t)0*128*N));
    float4 pw1 = __ldcs((const float4*)(Wp + (size_t)1*128*N));
    float4 pw2 = __ldcs((const float4*)(Wp + (size_t)2*128*N));
    float4 pw3 = __ldcs((const float4*)(Wp + (size_t)3*128*N));
    float4 pw4 = __ldcs((const float4*)(Wp + (size_t)4*128*N));
    float4 pw5 = __ldcs((const float4*)(Wp + (size_t)5*128*N));
    float4 pw6 = __ldcs((const float4*)(Wp + (size_t)6*128*N));
    float4 pw7 = __ldcs((const float4*)(Wp + (size_t)7*128*N));
    cudaGridDependencySynchronize();
    #pragma unroll
    for (int i = 0; i < ITER; i += 8) {
        float4 wv0 = (i == 0) ? pw0 : __ldcs((const float4*)(Wp + (size_t)(i+0)*128*N));
        float4 wv1 = (i == 0) ? pw1 : __ldcs((const float4*)(Wp + (size_t)(i+1)*128*N));
        float4 wv2 = (i == 0) ? pw2 : __ldcs((const float4*)(Wp + (size_t)(i+2)*128*N));
        float4 wv3 = (i == 0) ? pw3 : __ldcs((const float4*)(Wp + (size_t)(i+3)*128*N));
        float4 wv4 = (i == 0) ? pw4 : __ldcs((const float4*)(Wp + (size_t)(i+4)*128*N));
        float4 wv5 = (i == 0) ? pw5 : __ldcs((const float4*)(Wp + (size_t)(i+5)*128*N));
        float4 wv6 = (i == 0) ? pw6 : __ldcs((const float4*)(Wp + (size_t)(i+6)*128*N));
        float4 wv7 = (i == 0) ? pw7 : __ldcs((const float4*)(Wp + (size_t)(i+7)*128*N));
        float4 xv0 = *(const float4*)(xp + (size_t)(i+0)*128*Bb);
        float4 xv1 = *(const float4*)(xp + (size_t)(i+1)*128*Bb);
        float4 xv2 = *(const float4*)(xp + (size_t)(i+2)*128*Bb);
        float4 xv3 = *(const float4*)(xp + (size_t)(i+3)*128*Bb);
        float4 xv4 = *(const float4*)(xp + (size_t)(i+4)*128*Bb);
        float4 xv5 = *(const float4*)(xp + (size_t)(i+5)*128*Bb);
        float4 xv6 = *(const float4*)(xp + (size_t)(i+6)*128*Bb);
        float4 xv7 = *(const float4*)(xp + (size_t)(i+7)*128*Bb);
        GEMV_ACC(wv0, xv0)
        GEMV_ACC(wv1, xv1)
        GEMV_ACC(wv2, xv2)
        GEMV_ACC(wv3, xv3)
        GEMV_ACC(wv4, xv4)
        GEMV_ACC(wv5, xv5)
        GEMV_ACC(wv6, xv6)
        GEMV_ACC(wv7, xv7)
    }
    SHFL16(16) SHFL16(8) SHFL16(4) SHFL16(2)
    if (lane < 2) {
        float* s = smrow + (w*2 + tn)*17;
        s[0]=a0.x; s[1]=a0.y; s[2]=a0.z; s[3]=a0.w;
        s[4]=a1.x; s[5]=a1.y; s[6]=a1.z; s[7]=a1.w;
        s[8]=a2.x; s[9]=a2.y; s[10]=a2.z; s[11]=a2.w;
        s[12]=a3.x; s[13]=a3.y; s[14]=a3.z; s[15]=a3.w;
    }
}

template<int D, bool OUTBN>
__global__ void __launch_bounds__(256) gemv8_k(
    const float* __restrict__ x, const float* __restrict__ W,
    float* __restrict__ y, int N) {
    __shared__ float sred[16*17];
    int n0 = blockIdx.x * 8;
    gemv8_core<D>(x, W, N, n0, sred);
    __syncthreads();
    int tid = threadIdx.x;
    if (tid < 32) {
        int tno = tid >> 4, j = tid & 15;
        float s = 0.f;
        #pragma unroll
        for (int ww = 0; ww < 8; ww++) s += sred[(ww*2 + tno)*17 + j];
        int c = j >> 2, b = j & 3;
        int n = n0 + tno*4 + c;
        if (OUTBN) y[(size_t)b*N + n] = s;
        else       y[n*Bb + b] = s;
    }
}

// split-K GEMV: blockIdx.y = slice, writes partials to part[slice][N][B]
template<int DSLICE>
__global__ void __launch_bounds__(256) gemv8_splitk_k(
    const float* __restrict__ x, const float* __restrict__ W,
    float* __restrict__ part, int N) {
    __shared__ float sred[16*17];
    int slice = blockIdx.y;
    const float* xs = x + (size_t)slice*DSLICE*Bb;
    const float* Ws = W + (size_t)slice*DSLICE*N;
    int n0 = blockIdx.x * 8;
    gemv8_core<DSLICE>(xs, Ws, N, n0, sred);
    __syncthreads();
    int tid = threadIdx.x;
    if (tid < 32) {
        int tno = tid >> 4, j = tid & 15;
        float s = 0.f;
        #pragma unroll
        for (int ww = 0; ww < 8; ww++) s += sred[(ww*2 + tno)*17 + j];
        int c = j >> 2, b = j & 3;
        int n = n0 + tno*4 + c;
        part[((size_t)slice*N + n)*Bb + b] = s;
    }
}

// fused q/k/v projection: one launch, 512 blocks (q:256 k:128 v:128)
__global__ void __launch_bounds__(256) gemv8_qkv_k(
    const float* __restrict__ x, const float* __restrict__ wq,
    const float* __restrict__ wk, const float* __restrict__ wv,
    float* __restrict__ qkv) {
    __shared__ float sred[16*17];
    int nb = blockIdx.x;
    const float* W; float* y; int N, n0;
    if (nb < 256)      { W = wq; y = qkv;           N = 2048; n0 = nb*8; }
    else if (nb < 384) { W = wk; y = qkv + 2048*Bb; N = 1024; n0 = (nb-256)*8; }
    else               { W = wv; y = qkv + 3072*Bb; N = 1024; n0 = (nb-384)*8; }
    gemv8_core<Dm>(x, W, N, n0, sred);
    __syncthreads();
    int tid = threadIdx.x;
    if (tid < 32) {
        int tno = tid >> 4, j = tid & 15;
        float s = 0.f;
        #pragma unroll
        for (int ww = 0; ww < 8; ww++) s += sred[(ww*2 + tno)*17 + j];
        int c = j >> 2, b = j & 3;
        int n = n0 + tno*4 + c;
        y[n*Bb + b] = s;
    }
}

// fused gate/up GEMV + silu(g)*u, 8 cols/block -> 1024 blocks, 4-deep batches
__global__ void __launch_bounds__(256) gemv8_gateup_k(
    const float* __restrict__ x, const float* __restrict__ Wg,
    const float* __restrict__ Wu, float* __restrict__ y, int N) {
    __shared__ float sred[16*33];
    int tid = threadIdx.x;
    int tn = tid & 1, td = tid >> 1, w = tid >> 5, lane = tid & 31;
    int n0 = blockIdx.x * 8;
    const float* Wgp = Wg + n0 + tn*4 + (size_t)td*N;
    const float* Wup = Wu + n0 + tn*4 + (size_t)td*N;
    const float* xp = x + td*Bb;
    float4 ga0 = {0,0,0,0}, ga1 = ga0, ga2 = ga0, ga3 = ga0;
    float4 ua0 = ga0, ua1 = ga0, ua2 = ga0, ua3 = ga0;
    constexpr int ITER = Dm / 128;
    // ---- PDL prolog ----
    float4 pg0 = __ldcs((const float4*)(Wgp + (size_t)0*128*N));
    float4 pg1 = __ldcs((const float4*)(Wgp + (size_t)1*128*N));
    float4 pg2 = __ldcs((const float4*)(Wgp + (size_t)2*128*N));
    float4 pg3 = __ldcs((const float4*)(Wgp + (size_t)3*128*N));
    float4 pu0 = __ldcs((const float4*)(Wup + (size_t)0*128*N));
    float4 pu1 = __ldcs((const float4*)(Wup + (size_t)1*128*N));
    float4 pu2 = __ldcs((const float4*)(Wup + (size_t)2*128*N));
    float4 pu3 = __ldcs((const float4*)(Wup + (size_t)3*128*N));
    cudaGridDependencySynchronize();
    #pragma unroll
    for (int i = 0; i < ITER; i += 4) {
        float4 wg0 = (i == 0) ? pg0 : __ldcs((const float4*)(Wgp + (size_t)(i+0)*128*N));
        float4 wg1 = (i == 0) ? pg1 : __ldcs((const float4*)(Wgp + (size_t)(i+1)*128*N));
        float4 wg2 = (i == 0) ? pg2 : __ldcs((const float4*)(Wgp + (size_t)(i+2)*128*N));
        float4 wg3 = (i == 0) ? pg3 : __ldcs((const float4*)(Wgp + (size_t)(i+3)*128*N));
        float4 wu0 = (i == 0) ? pu0 : __ldcs((const float4*)(Wup + (size_t)(i+0)*128*N));
        float4 wu1 = (i == 0) ? pu1 : __ldcs((const float4*)(Wup + (size_t)(i+1)*128*N));
        float4 wu2 = (i == 0) ? pu2 : __ldcs((const float4*)(Wup + (size_t)(i+2)*128*N));
        float4 wu3 = (i == 0) ? pu3 : __ldcs((const float4*)(Wup + (size_t)(i+3)*128*N));
        float4 xv0 = *(const float4*)(xp + (size_t)(i+0)*128*Bb);
        float4 xv1 = *(const float4*)(xp + (size_t)(i+1)*128*Bb);
        float4 xv2 = *(const float4*)(xp + (size_t)(i+2)*128*Bb);
        float4 xv3 = *(const float4*)(xp + (size_t)(i+3)*128*Bb);
        {
            float4 &a0 = ga0, &a1 = ga1, &a2 = ga2, &a3 = ga3;
            GEMV_ACC(wg0, xv0)
            GEMV_ACC(wg1, xv1)
            GEMV_ACC(wg2, xv2)
            GEMV_ACC(wg3, xv3)
        }
        {
            float4 &a0 = ua0, &a1 = ua1, &a2 = ua2, &a3 = ua3;
            GEMV_ACC(wu0, xv0)
            GEMV_ACC(wu1, xv1)
            GEMV_ACC(wu2, xv2)
            GEMV_ACC(wu3, xv3)
        }
    }
    {
        float4 &a0 = ga0, &a1 = ga1, &a2 = ga2, &a3 = ga3;
        SHFL16(16) SHFL16(8) SHFL16(4) SHFL16(2)
    }
    {
        float4 &a0 = ua0, &a1 = ua1, &a2 = ua2, &a3 = ua3;
        SHFL16(16) SHFL16(8) SHFL16(4) SHFL16(2)
    }
    if (lane < 2) {
        float* s = &sred[(w*2 + tn)*33];
        s[0]=ga0.x; s[1]=ga0.y; s[2]=ga0.z; s[3]=ga0.w;
        s[4]=ga1.x; s[5]=ga1.y; s[6]=ga1.z; s[7]=ga1.w;
        s[8]=ga2.x; s[9]=ga2.y; s[10]=ga2.z; s[11]=ga2.w;
        s[12]=ga3.x; s[13]=ga3.y; s[14]=ga3.z; s[15]=ga3.w;
        s[16]=ua0.x; s[17]=ua0.y; s[18]=ua0.z; s[19]=ua0.w;
        s[20]=ua1.x; s[21]=ua1.y; s[22]=ua1.z; s[23]=ua1.w;
        s[24]=ua2.x; s[25]=ua2.y; s[26]=ua2.z; s[27]=ua2.w;
        s[28]=ua3.x; s[29]=ua3.y; s[30]=ua3.z; s[31]=ua3.w;
    }
    __syncthreads();
    if (tid < 32) {
        int tno = tid >> 4, j = tid & 15;
        float sg = 0.f, su = 0.f;
        #pragma unroll
        for (int ww = 0; ww < 8; ww++) {
            sg += sred[(ww*2 + tno)*33 + j];
            su += sred[(ww*2 + tno)*33 + 16 + j];
        }
        int c = j >> 2, b = j & 3;
        int n = n0 + tno*4 + c;
        float silu = sg / (1.f + __expf(-sg));
        y[n*Bb + b] = silu * su;
    }
}

// ---------------- fused rope + flash-decode attention ------------------------
__device__ __forceinline__ float dot4(float4 a, float4 b) {
    return a.x*b.x + a.y*b.y + a.z*b.z + a.w*b.w;
}

__global__ void __launch_bounds__(128) attn2_k(
    const float* __restrict__ kc, const float* __restrict__ vc,
    const int* __restrict__ cpos, const float* __restrict__ qkv,
    const float* __restrict__ qnw, const float* __restrict__ knw,
    float* __restrict__ pacc, float* __restrict__ pm, float* __restrict__ pl) {
    cudaGridDependencySynchronize();
    int bkv = blockIdx.x, chunk = blockIdx.y;
    int b = bkv >> 3, kv = bkv & 7;
    int t = threadIdx.x, w = t >> 5, lane = t & 31;
    int P = cpos[0];
    int n = P + 1;
    int csz = (n + NCHUNK - 1) / NCHUNK;
    int start = chunk * csz;
    int end = min(start + csz, n);
    int bh0 = b*Hh + kv*2;
    if (start >= n) {   // empty chunk (only when n < NCHUNK)
        for (int i = t; i < 2*HD; i += 128) {
            int hh = i >> 7, tt = i & 127;
            pacc[((size_t)(bh0 + hh)*NCHUNK + chunk)*HD + tt] = 0.f;
        }
        if (t < 2) {
            pm[(bh0 + t)*NCHUNK + chunk] = -1e30f;
            pl[(bh0 + t)*NCHUNK + chunk] = 0.f;
        }
        return;
    }

    // ---- inline per-head rmsnorm + rope of q0,q1,k (and v passthrough) ----
    float q0 = qkv[((kv*2    )*HD + t)*Bb + b];
    float q1 = qkv[((kv*2 + 1)*HD + t)*Bb + b];
    float kkv = qkv[(2048 + kv*HD + t)*Bb + b];
    float vvv = qkv[(3072 + kv*HD + t)*Bb + b];
    __shared__ float red[3][4];
    float s0 = q0*q0, s1 = q1*q1, s2 = kkv*kkv;
    #pragma unroll
    for (int o = 16; o; o >>= 1) {
        s0 += __shfl_xor_sync(~0u, s0, o);
        s1 += __shfl_xor_sync(~0u, s1, o);
        s2 += __shfl_xor_sync(~0u, s2, o);
    }
    if (lane == 0) { red[0][w] = s0; red[1][w] = s1; red[2][w] = s2; }
    __syncthreads();
    float r0 = rsqrtf((red[0][0]+red[0][1]+red[0][2]+red[0][3])/(float)HD + EPS);
    float r1 = rsqrtf((red[1][0]+red[1][1]+red[1][2]+red[1][3])/(float)HD + EPS);
    float r2 = rsqrtf((red[2][0]+red[2][1]+red[2][2]+red[2][3])/(float)HD + EPS);
    float qw_ = qnw[t], kw_ = knw[t];
    q0 *= r0*qw_; q1 *= r1*qw_; kkv *= r2*kw_;
    __shared__ __align__(16) float sq0[HD], sq1[HD], sk[HD], sv[HD];
    sq0[t] = q0; sq1[t] = q1; sk[t] = kkv;
    __syncthreads();
    {
        int i = t & 63;
        float inv = __expf(-(float)i * ROPE_C);
        float ang = (float)P * inv;
        float sn, cs;
        __sincosf(ang, &sn, &cs);
        float o0, o1, ok;
        if (t < 64) { o0 = q0*cs - sq0[t+64]*sn; o1 = q1*cs - sq1[t+64]*sn; ok = kkv*cs - sk[t+64]*sn; }
        else        { o0 = q0*cs + sq0[t-64]*sn; o1 = q1*cs + sq1[t-64]*sn; ok = kkv*cs + sk[t-64]*sn; }
        __syncthreads();
        sq0[t] = o0; sq1[t] = o1; sk[t] = ok; sv[t] = vvv;
    }
    __syncthreads();

    // ---- flash-decode over this chunk (scale folded into q) ----
    float4 qf0 = *(const float4*)(sq0 + lane*4);
    float4 qf1 = *(const float4*)(sq1 + lane*4);
    qf0.x *= ATT_SCALE; qf0.y *= ATT_SCALE; qf0.z *= ATT_SCALE; qf0.w *= ATT_SCALE;
    qf1.x *= ATT_SCALE; qf1.y *= ATT_SCALE; qf1.z *= ATT_SCALE; qf1.w *= ATT_SCALE;
    const float* Kbase = kc + ((size_t)b*KVh + kv)*MAXP*HD;
    const float* Vbase = vc + ((size_t)b*KVh + kv)*MAXP*HD;
    float m0 = -1e30f, m1 = -1e30f, l0 = 0.f, l1 = 0.f;
    float4 a0 = {0,0,0,0}, a1 = a0;
    int endEx = min(end, P);   // exclusive of new-token position P
    int p = start + w;
    // ---- main: 2 positions per warp-iteration (p and p+4), fused update ----
    for (; p + 4 < endEx; p += 8) {
        float4 ka = __ldcs((const float4*)(Kbase + (size_t)p*HD) + lane);
        float4 kb = __ldcs((const float4*)(Kbase + (size_t)(p+4)*HD) + lane);
        float4 va = __ldcs((const float4*)(Vbase + (size_t)p*HD) + lane);
        float4 vb = __ldcs((const float4*)(Vbase + (size_t)(p+4)*HD) + lane);
        float d0a = dot4(qf0, ka), d1a = dot4(qf1, ka);
        float d0b = dot4(qf0, kb), d1b = dot4(qf1, kb);
        #pragma unroll
        for (int o = 16; o; o >>= 1) {
            d0a += __shfl_xor_sync(~0u, d0a, o);
            d1a += __shfl_xor_sync(~0u, d1a, o);
            d0b += __shfl_xor_sync(~0u, d0b, o);
            d1b += __shfl_xor_sync(~0u, d1b, o);
        }
        {
            float mn = fmaxf(m0, fmaxf(d0a, d0b));
            float c  = __expf(m0 - mn);
            float pa = __expf(d0a - mn), pb = __expf(d0b - mn);
            l0 = l0*c + pa + pb;
            a0.x = a0.x*c + pa*va.x + pb*vb.x;
            a0.y = a0.y*c + pa*va.y + pb*vb.y;
            a0.z = a0.z*c + pa*va.z + pb*vb.z;
            a0.w = a0.w*c + pa*va.w + pb*vb.w;
            m0 = mn;
        }
        {
            float mn = fmaxf(m1, fmaxf(d1a, d1b));
            float c  = __expf(m1 - mn);
            float pa = __expf(d1a - mn), pb = __expf(d1b - mn);
            l1 = l1*c + pa + pb;
            a1.x = a1.x*c + pa*va.x + pb*vb.x;
            a1.y = a1.y*c + pa*va.y + pb*vb.y;
            a1.z = a1.z*c + pa*va.z + pb*vb.z;
            a1.w = a1.w*c + pa*va.w + pb*vb.w;
            m1 = mn;
        }
    }
    // ---- tail: single position ----
    for (; p < endEx; p += 4) {
        float4 kk = __ldcs((const float4*)(Kbase + (size_t)p*HD) + lane);
        float4 vv = __ldcs((const float4*)(Vbase + (size_t)p*HD) + lane);
        float d0 = dot4(qf0, kk), d1 = dot4(qf1, kk);
        #pragma unroll
        for (int o = 16; o; o >>= 1) {
            d0 += __shfl_xor_sync(~0u, d0, o);
            d1 += __shfl_xor_sync(~0u, d1, o);
        }
        float mn0 = fmaxf(m0, d0), c0 = __expf(m0 - mn0), p0 = __expf(d0 - mn0);
        l0 = l0*c0 + p0;
        a0.x = a0.x*c0 + p0*vv.x; a0.y = a0.y*c0 + p0*vv.y;
        a0.z = a0.z*c0 + p0*vv.z; a0.w = a0.w*c0 + p0*vv.w;
        m0 = mn0;
        float mn1 = fmaxf(m1, d1), c1 = __expf(m1 - mn1), p1 = __expf(d1 - mn1);
        l1 = l1*c1 + p1;
        a1.x = a1.x*c1 + p1*vv.x; a1.y = a1.y*c1 + p1*vv.y;
        a1.z = a1.z*c1 + p1*vv.z; a1.w = a1.w*c1 + p1*vv.w;
        m1 = mn1;
    }
    // ---- new-token position P (from shared), if in this chunk ----
    if (P >= start && P < end && w == ((P - start) & 3)) {
        float4 kk = *(const float4*)(sk + lane*4);
        float4 vv = *(const float4*)(sv + lane*4);
        float d0 = dot4(qf0, kk), d1 = dot4(qf1, kk);
        #pragma unroll
        for (int o = 16; o; o >>= 1) {
            d0 += __shfl_xor_sync(~0u, d0, o);
            d1 += __shfl_xor_sync(~0u, d1, o);
        }
        float mn0 = fmaxf(m0, d0), c0 = __expf(m0 - mn0), p0 = __expf(d0 - mn0);
        l0 = l0*c0 + p0;
        a0.x = a0.x*c0 + p0*vv.x; a0.y = a0.y*c0 + p0*vv.y;
        a0.z = a0.z*c0 + p0*vv.z; a0.w = a0.w*c0 + p0*vv.w;
        m0 = mn0;
        float mn1 = fmaxf(m1, d1), c1 = __expf(m1 - mn1), p1 = __expf(d1 - mn1);
        l1 = l1*c1 + p1;
        a1.x = a1.x*c1 + p1*vv.x; a1.y = a1.y*c1 + p1*vv.y;
        a1.z = a1.z*c1 + p1*vv.z; a1.w = a1.w*c1 + p1*vv.w;
        m1 = mn1;
    }

    __shared__ float sm_m[2][4], sm_l[2][4];
    __shared__ float sm_a[2][4][HD];
    if (lane == 0) { sm_m[0][w] = m0; sm_l[0][w] = l0; sm_m[1][w] = m1; sm_l[1][w] = l1; }
    *(float4*)&sm_a[0][w][lane*4] = a0;
    *(float4*)&sm_a[1][w][lane*4] = a1;
    __syncthreads();
    #pragma unroll
    for (int hh = 0; hh < 2; hh++) {
        float M = fmaxf(fmaxf(sm_m[hh][0], sm_m[hh][1]), fmaxf(sm_m[hh][2], sm_m[hh][3]));
        float L = 0.f, A = 0.f;
        #pragma unroll
        for (int ww = 0; ww < 4; ww++) {
            float e = __expf(sm_m[hh][ww] - M);
            L += sm_l[hh][ww] * e;
            A += sm_a[hh][ww][t] * e;
        }
        pacc[((size_t)(bh0 + hh)*NCHUNK + chunk)*HD + t] = A;
        if (t == 0) {
            pm[(bh0 + hh)*NCHUNK + chunk] = M;
            pl[(bh0 + hh)*NCHUNK + chunk] = L;
        }
    }
}

__global__ void attn_comb_k(const float* __restrict__ pacc, const float* __restrict__ pm,
                            const float* __restrict__ pl, float* __restrict__ o) {
    cudaGridDependencySynchronize();
    int bh = blockIdx.x, t = threadIdx.x;
    int b = bh / Hh, h = bh % Hh;
    float M = -1e30f;
    #pragma unroll
    for (int c = 0; c < NCHUNK; c++) M = fmaxf(M, pm[bh*NCHUNK + c]);
    float L = 0.f, A = 0.f;
    #pragma unroll
    for (int c = 0; c < NCHUNK; c++) {
        float e = __expf(pm[bh*NCHUNK + c] - M);
        L += pl[bh*NCHUNK + c] * e;
        A += pacc[((size_t)bh*NCHUNK + c)*HD + t] * e;
    }
    o[(h*HD + t)*Bb + b] = A / L;
}

// ---------------- PDL launch helper ------------------------------------------
template <typename... Args, typename... Ts>
static void pdl_launch(void (*kern)(Args...), dim3 grid, dim3 block, Ts... args) {
    cudaLaunchConfig_t cfg = {};
    cfg.gridDim = grid;
    cfg.blockDim = block;
    cfg.dynamicSmemBytes = 0;
    cfg.stream = 0;
    cudaLaunchAttribute at[1];
    at[0].id = cudaLaunchAttributeProgrammaticStreamSerialization;
    at[0].val.programmaticStreamSerializationAllowed = 1;
    cfg.attrs = at;
    cfg.numAttrs = 1;
    cudaLaunchKernelEx(&cfg, kern, static_cast<Args>(args)...);
}

// ---------------- host orchestration ----------------------------------------
extern "C" void kernel_launch(void* const* d_in, const int* in_sizes, int n_in,
                              void* d_out, int out_size) {
    const int*   tok    = (const int*)  d_in[0];
    const int*   cpos   = (const int*)  d_in[1];
    const float* kcache = (const float*)d_in[2];
    const float* vcache = (const float*)d_in[3];
    const float* embw   = (const float*)d_in[4];
    const float* ln1    = (const float*)d_in[5];
    const float* wq     = (const float*)d_in[6];
    const float* wk     = (const float*)d_in[7];
    const float* wv     = (const float*)d_in[8];
    const float* qnw    = (const float*)d_in[9];
    const float* knw    = (const float*)d_in[10];
    const float* wo     = (const float*)d_in[11];
    const float* ln2    = (const float*)d_in[12];
    const float* wg     = (const float*)d_in[13];
    const float* wu     = (const float*)d_in[14];
    const float* wd     = (const float*)d_in[15];
    const float* fnw    = (const float*)d_in[16];
    const float* lmw    = (const float*)d_in[17];
    float* out = (float*)d_out;

    float *x, *x2, *h, *qkv, *o, *g, *part, *pacc, *pm, *pl;
    cudaGetSymbolAddress((void**)&x,    g_x);
    cudaGetSymbolAddress((void**)&x2,   g_x2);
    cudaGetSymbolAddress((void**)&h,    g_h);
    cudaGetSymbolAddress((void**)&qkv,  g_qkv);
    cudaGetSymbolAddress((void**)&o,    g_o);
    cudaGetSymbolAddress((void**)&g,    g_g);
    cudaGetSymbolAddress((void**)&part, g_part);
    cudaGetSymbolAddress((void**)&pacc, g_pacc);
    cudaGetSymbolAddress((void**)&pm,   g_pm);
    cudaGetSymbolAddress((void**)&pl,   g_pl);

    float* xa = x;
    float* xb = x2;

    for (int l = 0; l < Ll; l++) {
        const float* wq_l = wq + (size_t)l*Dm*Hh*HD;
        const float* wk_l = wk + (size_t)l*Dm*KVh*HD;
        const float* wv_l = wv + (size_t)l*Dm*KVh*HD;
        const float* wo_l = wo + (size_t)l*Hh*HD*Dm;
        const float* wg_l = wg + (size_t)l*Dm*Ff;
        const float* wu_l = wu + (size_t)l*Dm*Ff;
        const float* wd_l = wd + (size_t)l*Ff*Dm;
        const float* kc_l = kcache + (size_t)l*Bb*KVh*MAXP*HD;
        const float* vc_l = vcache + (size_t)l*Bb*KVh*MAXP*HD;

        if (l == 0) {
            pdl_launch(rms_embed_k, dim3(8), dim3(256), tok, embw, ln1 + l*Dm, xa, h);
        } else {
            // absorb previous layer's down-proj partials into residual
            pdl_launch(rms_add_k, dim3(8), dim3(256), xa, part, ln1 + l*Dm, xb, h);
            float* tmp = xa; xa = xb; xb = tmp;
        }
        pdl_launch(gemv8_qkv_k, dim3(512), dim3(256), h, wq_l, wk_l, wv_l, qkv);
        pdl_launch(attn2_k, dim3(Bb*KVh, NCHUNK), dim3(128), kc_l, vc_l, cpos, qkv,
                   qnw + l*HD, knw + l*HD, pacc, pm, pl);
        pdl_launch(attn_comb_k, dim3(Bb*Hh), dim3(HD), pacc, pm, pl, o);
        pdl_launch(gemv8_splitk_k<1024>, dim3(256, 2), dim3(256), o, wo_l, part, 2048);
        pdl_launch(rms_add_k, dim3(8), dim3(256), xa, part, ln2 + l*Dm, xb, h);
        { float* tmp = xa; xa = xb; xb = tmp; }
        pdl_launch(gemv8_gateup_k, dim3(Ff/8), dim3(256), h, wg_l, wu_l, g, Ff);
        pdl_launch(gemv8_splitk_k<4096>, dim3(256, 2), dim3(256), g, wd_l, part, 2048);
    }

    pdl_launch(rms_add_k, dim3(8), dim3(256), xa, part, fnw, xb, h);
    pdl_launch(gemv8_k<Dm, true>, dim3(Vv/8), dim3(256), h, lmw, out, Vv);
}